// round 2
// baseline (speedup 1.0000x reference)
#include <cuda_runtime.h>
#include <limits.h>
#include <stdint.h>

typedef unsigned long long u64;

// Problem constants
#define BATCH 32
#define NPTS  131072            // 2^17
#define BN    (BATCH*NPTS)      // 4194304
#define TSEL  32768
#define CELL  0.05f

// Hash: 2^23 slots of one u64 (key<<32 | minIndex), load factor <= 0.5
#define HBITS 23
#define HSIZE (1<<HBITS)
#define HMASK (HSIZE-1)
#define EMPTY64 0xFFFFFFFFFFFFFFFFull

// Scan config: 1024 blocks x 4096 elements (256 thr x 16)
#define NBLK  1024
#define CHUNK 4096
#define SCANT 256
#define ITEMS 16

// Output layout (flattened, concatenated, all f32)
#define OFF_Y    0
#define OFF_IDX  (BATCH*TSEL*3)
#define OFF_MASK (OFF_IDX + BATCH*TSEL*2)
#define OFF_UL   (OFF_MASK + BATCH*TSEL)
#define OFF_ULI  (OFF_UL + BN)

// Scratch
__device__ u64 d_h[HSIZE];             // 64MB: (key<<32)|minIdx ; low word later = rank
__device__ int d_slot[BN];             // 16MB
__device__ unsigned d_key[BN];         // 16MB
__device__ unsigned d_flag[BN/4];      // 4MB, 4 flags per word (byte lanes)
__device__ int d_bsum[NBLK];
__device__ int d_boff[NBLK];
__device__ int d_pbatch[BATCH+1];

__device__ __forceinline__ int quant(float v) {
    return (int)rintf(__fdiv_rn(v, CELL));
}
__device__ __forceinline__ unsigned mkkey(int b, int q0, int q1, int q2) {
    return ((unsigned)b << 27) | ((unsigned)(q0 + 256) << 18)
         | ((unsigned)(q1 + 256) << 9) | (unsigned)(q2 + 256);
}
__device__ __forceinline__ unsigned khash(unsigned k) {
    return (k * 2654435761u) >> (32 - HBITS);
}

// ---------------------------------------------------------------------------
// K1: init hash table to EMPTY
__global__ void k_init() {
    unsigned i = blockIdx.x * blockDim.x + threadIdx.x;
    unsigned stride = gridDim.x * blockDim.x;
    ulonglong2* p = (ulonglong2*)d_h;
    const unsigned n = HSIZE / 2;
    for (unsigned j = i; j < n; j += stride)
        p[j] = make_ulonglong2(EMPTY64, EMPTY64);
}

// ---------------------------------------------------------------------------
// K2: insert, 4 points per thread with coalesced float4 loads
__global__ void k_insert(const float* __restrict__ x) {
    int j = blockIdx.x * blockDim.x + threadIdx.x;   // [0, BN/4)
    const float4* xv = (const float4*)x;
    float4 a = __ldg(&xv[3*j+0]);
    float4 b4 = __ldg(&xv[3*j+1]);
    float4 c = __ldg(&xv[3*j+2]);
    float px[12] = {a.x,a.y,a.z,a.w, b4.x,b4.y,b4.z,b4.w, c.x,c.y,c.z,c.w};

    int base = 4 * j;
    int b = base >> 17;                              // 4 points share batch (N mult of 4)
    int slots[4];
    #pragma unroll
    for (int e = 0; e < 4; e++) {
        int q0 = quant(px[3*e+0]);
        int q1 = quant(px[3*e+1]);
        int q2 = quant(px[3*e+2]);
        unsigned key = mkkey(b, q0, q1, q2);
        int i = base + e;
        u64 val = ((u64)key << 32) | (unsigned)i;
        unsigned h = khash(key);
        while (true) {
            u64 cur = __ldcg(&d_h[h]);
            unsigned hi = (unsigned)(cur >> 32);
            if (hi == key) { atomicMin(&d_h[h], val); break; }
            if (cur == EMPTY64) {
                u64 old = atomicCAS(&d_h[h], EMPTY64, val);
                if (old == EMPTY64) break;
                if ((unsigned)(old >> 32) == key) { atomicMin(&d_h[h], val); break; }
            }
            h = (h + 1) & HMASK;
        }
        slots[e] = (int)h;
    }
    *(int4*)(d_slot + base) = make_int4(slots[0], slots[1], slots[2], slots[3]);
}

// ---------------------------------------------------------------------------
// K3: flags + keys + per-block sums
__global__ void k_flags() {
    int t = threadIdx.x;
    int i0 = blockIdx.x * CHUNK + t * ITEMS;
    int s = 0;
    unsigned fw[4];
    #pragma unroll
    for (int v = 0; v < 4; v++) {
        int4 sl = *(const int4*)(d_slot + i0 + 4*v);
        u64 c0 = __ldg(&d_h[sl.x]);
        u64 c1 = __ldg(&d_h[sl.y]);
        u64 c2 = __ldg(&d_h[sl.z]);
        u64 c3 = __ldg(&d_h[sl.w]);
        unsigned f0 = ((unsigned)c0 == (unsigned)(i0 + 4*v + 0));
        unsigned f1 = ((unsigned)c1 == (unsigned)(i0 + 4*v + 1));
        unsigned f2 = ((unsigned)c2 == (unsigned)(i0 + 4*v + 2));
        unsigned f3 = ((unsigned)c3 == (unsigned)(i0 + 4*v + 3));
        *(uint4*)(d_key + i0 + 4*v) = make_uint4(
            (unsigned)(c0 >> 32), (unsigned)(c1 >> 32),
            (unsigned)(c2 >> 32), (unsigned)(c3 >> 32));
        fw[v] = f0 | (f1 << 8) | (f2 << 16) | (f3 << 24);
        s += (int)(f0 + f1 + f2 + f3);
    }
    *(uint4*)(d_flag + i0/4) = make_uint4(fw[0], fw[1], fw[2], fw[3]);

    #pragma unroll
    for (int o = 16; o; o >>= 1) s += __shfl_xor_sync(0xFFFFFFFFu, s, o);
    __shared__ int ws[8];
    int lane = t & 31, wid = t >> 5;
    if (lane == 0) ws[wid] = s;
    __syncthreads();
    if (t == 0) {
        int tot = 0;
        #pragma unroll
        for (int k = 0; k < 8; k++) tot += ws[k];
        d_bsum[blockIdx.x] = tot;
    }
}

// ---------------------------------------------------------------------------
// K4: scan the 1024 block sums; per-block offsets + per-batch boundaries
__global__ void k_scan2() {
    __shared__ int sh[NBLK];
    int t = threadIdx.x;
    int v = d_bsum[t];
    sh[t] = v;
    __syncthreads();
    for (int o = 1; o < NBLK; o <<= 1) {
        int add = (t >= o) ? sh[t - o] : 0;
        __syncthreads();
        sh[t] += add;
        __syncthreads();
    }
    int incl = sh[t];
    int excl = incl - v;
    d_boff[t] = excl;
    if ((t & 31) == 0) d_pbatch[t >> 5] = excl;   // N/CHUNK = 32 blocks per batch
    if (t == NBLK - 1) d_pbatch[BATCH] = incl;
}

// ---------------------------------------------------------------------------
// K5: final — prefix per point, rank scatter (into d_h low word), ul_idx_inv,
//     per-batch stable-partition top-T select, y from key
__global__ void k_final(float* __restrict__ out) {
    __shared__ int pb[BATCH + 1];
    __shared__ int wsum[8];
    __shared__ int wexc[8];
    int t = threadIdx.x;
    if (t <= BATCH) pb[t] = d_pbatch[t];

    int i0 = blockIdx.x * CHUNK + t * ITEMS;
    uint4 v4 = *(const uint4*)(d_flag + i0/4);
    unsigned w[4] = {v4.x, v4.y, v4.z, v4.w};

    unsigned kk[ITEMS];
    #pragma unroll
    for (int v = 0; v < 4; v++) {
        uint4 kv = *(const uint4*)(d_key + i0 + 4*v);
        kk[4*v+0] = kv.x; kk[4*v+1] = kv.y; kk[4*v+2] = kv.z; kk[4*v+3] = kv.w;
    }
    int ss[ITEMS];
    #pragma unroll
    for (int v = 0; v < 4; v++) {
        int4 sv = *(const int4*)(d_slot + i0 + 4*v);
        ss[4*v+0] = sv.x; ss[4*v+1] = sv.y; ss[4*v+2] = sv.z; ss[4*v+3] = sv.w;
    }

    int pre[ITEMS];
    int c = 0;
    #pragma unroll
    for (int e = 0; e < ITEMS; e++) {
        pre[e] = c;
        c += (int)((w[e >> 2] >> ((e & 3) * 8)) & 1);
    }
    int lane = t & 31, wid = t >> 5;
    int inc = c;
    #pragma unroll
    for (int o = 1; o < 32; o <<= 1) {
        int u = __shfl_up_sync(0xFFFFFFFFu, inc, o);
        if (lane >= o) inc += u;
    }
    if (lane == 31) wsum[wid] = inc;
    __syncthreads();
    if (t < 8) {
        int val = wsum[t];
        int ic = val;
        #pragma unroll
        for (int o = 1; o < 8; o <<= 1) {
            int u = __shfl_up_sync(0xFFu, ic, o);
            if (t >= o) ic += u;
        }
        wexc[t] = ic - val;
    }
    __syncthreads();
    int thOff = d_boff[blockIdx.x] + wexc[wid] + (inc - c);

    unsigned* hw = (unsigned*)d_h;  // low words: rank storage

    #pragma unroll
    for (int e = 0; e < ITEMS; e++) {
        int i   = i0 + e;
        int isf = (int)((w[e >> 2] >> ((e & 3) * 8)) & 1);
        int p   = thOff + pre[e];
        int b   = i >> 17;
        int il  = i & (NPTS - 1);
        int r   = p - pb[b];
        int Kb  = pb[b + 1] - pb[b];
        int sel;
        if (isf) {
            hw[2 * ss[e]] = (unsigned)p;        // appearance rank into hash low word
            out[OFF_ULI + p] = (float)i;        // ul_idx_inv (p monotone in i)
            sel = (r < TSEL) ? r : -1;
        } else {
            int tt = Kb + (il - r);
            sel = (tt < TSEL) ? tt : -1;
        }
        if (sel >= 0) {
            unsigned key = kk[e];
            float y0 = CELL * (float)((int)((key >> 18) & 511) - 256);
            float y1 = CELL * (float)((int)((key >> 9) & 511) - 256);
            float y2 = CELL * (float)((int)(key & 511) - 256);
            int o = b * TSEL + sel;
            out[OFF_Y + 3*o + 0] = y0;
            out[OFF_Y + 3*o + 1] = y1;
            out[OFF_Y + 3*o + 2] = y2;
            out[OFF_IDX + 2*o + 0] = (float)b;
            out[OFF_IDX + 2*o + 1] = (float)il;
            out[OFF_MASK + o] = isf ? 1.0f : 0.0f;
        }
    }
}

// ---------------------------------------------------------------------------
// K6: ul_idx gather + SENT tail of ul_idx_inv, 4 points per thread
__global__ void k_ulidx(float* __restrict__ out) {
    int j = blockIdx.x * blockDim.x + threadIdx.x;   // [0, BN/4)
    int base = 4 * j;
    int U = d_pbatch[BATCH];
    const unsigned* hw = (const unsigned*)d_h;
    int4 sl = *(const int4*)(d_slot + base);
    float r0 = (float)__ldg(hw + 2*sl.x);
    float r1 = (float)__ldg(hw + 2*sl.y);
    float r2 = (float)__ldg(hw + 2*sl.z);
    float r3 = (float)__ldg(hw + 2*sl.w);
    *(float4*)(out + OFF_UL + base) = make_float4(r0, r1, r2, r3);
    // SENT tail for ul_idx_inv
    #pragma unroll
    for (int e = 0; e < 4; e++) {
        int i = base + e;
        if (i >= U) out[OFF_ULI + i] = (float)BN;
    }
}

// ---------------------------------------------------------------------------
extern "C" void kernel_launch(void* const* d_in, const int* in_sizes, int n_in,
                              void* d_out, int out_size) {
    const float* x = (const float*)d_in[0];
    float* out = (float*)d_out;
    (void)in_sizes; (void)n_in; (void)out_size;

    k_init  <<<2048, 512>>>();
    k_insert<<<BN / 4 / 256, 256>>>(x);
    k_flags <<<NBLK, SCANT>>>();
    k_scan2 <<<1, NBLK>>>();
    k_final <<<NBLK, SCANT>>>(out);
    k_ulidx <<<BN / 4 / 256, 256>>>(out);
}

// round 3
// speedup vs baseline: 1.3248x; 1.3248x over previous
#include <cuda_runtime.h>
#include <limits.h>
#include <stdint.h>

typedef unsigned long long u64;

// Problem constants
#define BATCH 32
#define NPTS  131072            // 2^17
#define BN    (BATCH*NPTS)      // 4194304
#define TSEL  32768
#define CELL  0.05f

// Hash: 2^23 slots of one u64 (key<<32 | minIndex), load factor <= 0.5
#define HBITS 23
#define HSIZE (1<<HBITS)
#define HMASK (HSIZE-1)
#define EMPTY64 0xFFFFFFFFFFFFFFFFull

// Scan config: 1024 blocks x 4096 elements (256 thr x 16)
#define NBLK  1024
#define CHUNK 4096
#define SCANT 256
#define ITEMS 16

// Output layout (flattened, concatenated, all f32)
#define OFF_Y    0
#define OFF_IDX  (BATCH*TSEL*3)
#define OFF_MASK (OFF_IDX + BATCH*TSEL*2)
#define OFF_UL   (OFF_MASK + BATCH*TSEL)
#define OFF_ULI  (OFF_UL + BN)

// Scratch
__device__ u64 d_h[HSIZE];             // (key<<32)|minIdx ; low word later = rank
__device__ int d_slot[BN];
__device__ unsigned char d_flag[BN];
__device__ int d_bsum[NBLK];
__device__ int d_boff[NBLK];
__device__ int d_pbatch[BATCH+1];

__device__ __forceinline__ int quant(float v) {
    return (int)rintf(__fdiv_rn(v, CELL));
}
__device__ __forceinline__ unsigned mkkey(int b, int q0, int q1, int q2) {
    return ((unsigned)b << 27) | ((unsigned)(q0 + 256) << 18)
         | ((unsigned)(q1 + 256) << 9) | (unsigned)(q2 + 256);
}
__device__ __forceinline__ unsigned khash(unsigned k) {
    return (k * 2654435761u) >> (32 - HBITS);
}

// ---------------------------------------------------------------------------
// K1: init hash table to EMPTY
__global__ void k_init() {
    unsigned i = blockIdx.x * blockDim.x + threadIdx.x;
    unsigned stride = gridDim.x * blockDim.x;
    ulonglong2* p = (ulonglong2*)d_h;
    const unsigned n = HSIZE / 2;
    for (unsigned j = i; j < n; j += stride)
        p[j] = make_ulonglong2(EMPTY64, EMPTY64);
}

// ---------------------------------------------------------------------------
// K2: insert, 1 point per thread (max TLP on the probe chain)
__global__ void k_insert(const float* __restrict__ x) {
    int i = blockIdx.x * blockDim.x + threadIdx.x;   // [0, BN)
    float x0 = __ldg(&x[3*i+0]);
    float x1 = __ldg(&x[3*i+1]);
    float x2 = __ldg(&x[3*i+2]);
    int q0 = quant(x0), q1 = quant(x1), q2 = quant(x2);
    int b = i >> 17;
    unsigned key = mkkey(b, q0, q1, q2);
    u64 val = ((u64)key << 32) | (unsigned)i;
    unsigned h = khash(key);
    while (true) {
        u64 cur = __ldcg(&d_h[h]);
        unsigned hi = (unsigned)(cur >> 32);
        if (hi == key) { atomicMin(&d_h[h], val); break; }
        if (cur == EMPTY64) {
            u64 old = atomicCAS(&d_h[h], EMPTY64, val);
            if (old == EMPTY64) break;                      // claimed: no min needed
            if ((unsigned)(old >> 32) == key) { atomicMin(&d_h[h], val); break; }
        }
        h = (h + 1) & HMASK;
    }
    d_slot[i] = (int)h;
}

// ---------------------------------------------------------------------------
// K3: first-occurrence flags (packed 16B store) + per-block sums
__global__ void k_flags() {
    int t = threadIdx.x;
    int i0 = blockIdx.x * CHUNK + t * ITEMS;
    int s = 0;
    unsigned fw[4];
    #pragma unroll
    for (int v = 0; v < 4; v++) {
        int4 sl = *(const int4*)(d_slot + i0 + 4*v);
        u64 c0 = __ldcg(&d_h[sl.x]);
        u64 c1 = __ldcg(&d_h[sl.y]);
        u64 c2 = __ldcg(&d_h[sl.z]);
        u64 c3 = __ldcg(&d_h[sl.w]);
        unsigned f0 = ((unsigned)c0 == (unsigned)(i0 + 4*v + 0));
        unsigned f1 = ((unsigned)c1 == (unsigned)(i0 + 4*v + 1));
        unsigned f2 = ((unsigned)c2 == (unsigned)(i0 + 4*v + 2));
        unsigned f3 = ((unsigned)c3 == (unsigned)(i0 + 4*v + 3));
        fw[v] = f0 | (f1 << 8) | (f2 << 16) | (f3 << 24);
        s += (int)(f0 + f1 + f2 + f3);
    }
    *(uint4*)(d_flag + i0) = make_uint4(fw[0], fw[1], fw[2], fw[3]);

    #pragma unroll
    for (int o = 16; o; o >>= 1) s += __shfl_xor_sync(0xFFFFFFFFu, s, o);
    __shared__ int ws[8];
    int lane = t & 31, wid = t >> 5;
    if (lane == 0) ws[wid] = s;
    __syncthreads();
    if (t == 0) {
        int tot = 0;
        #pragma unroll
        for (int k = 0; k < 8; k++) tot += ws[k];
        d_bsum[blockIdx.x] = tot;
    }
}

// ---------------------------------------------------------------------------
// K4: warp-shuffle scan of the 1024 block sums
__global__ void k_scan2() {
    __shared__ int wsum[32];
    int t = threadIdx.x;
    int lane = t & 31, wid = t >> 5;
    int v = d_bsum[t];
    int inc = v;
    #pragma unroll
    for (int o = 1; o < 32; o <<= 1) {
        int u = __shfl_up_sync(0xFFFFFFFFu, inc, o);
        if (lane >= o) inc += u;
    }
    if (lane == 31) wsum[wid] = inc;
    __syncthreads();
    if (t < 32) {
        int wv = wsum[t];
        int wi = wv;
        #pragma unroll
        for (int o = 1; o < 32; o <<= 1) {
            int u = __shfl_up_sync(0xFFFFFFFFu, wi, o);
            if (t >= o) wi += u;
        }
        wsum[t] = wi - wv;   // exclusive warp offset
    }
    __syncthreads();
    int incl = inc + wsum[wid];
    int excl = incl - v;
    d_boff[t] = excl;
    if ((t & 31) == 0) d_pbatch[t >> 5] = excl;   // 32 blocks per batch
    if (t == NBLK - 1) d_pbatch[BATCH] = incl;
}

// ---------------------------------------------------------------------------
// K5: final — prefix per point, rank scatter (hash low word), ul_idx_inv +
//     SENT tail, per-batch stable-partition top-T select (y via x gather)
__global__ void k_final(const float* __restrict__ x, float* __restrict__ out) {
    __shared__ int pb[BATCH + 1];
    __shared__ int wsum[8];
    __shared__ int wexc[8];
    int t = threadIdx.x;
    if (t <= BATCH) pb[t] = d_pbatch[t];

    int i0 = blockIdx.x * CHUNK + t * ITEMS;
    uint4 v4 = *(const uint4*)(d_flag + i0);
    unsigned w[4] = {v4.x, v4.y, v4.z, v4.w};

    int ss[ITEMS];
    #pragma unroll
    for (int v = 0; v < 4; v++) {
        int4 sv = *(const int4*)(d_slot + i0 + 4*v);
        ss[4*v+0] = sv.x; ss[4*v+1] = sv.y; ss[4*v+2] = sv.z; ss[4*v+3] = sv.w;
    }

    int pre[ITEMS];
    int c = 0;
    #pragma unroll
    for (int e = 0; e < ITEMS; e++) {
        pre[e] = c;
        c += (int)((w[e >> 2] >> ((e & 3) * 8)) & 1);
    }
    int lane = t & 31, wid = t >> 5;
    int inc = c;
    #pragma unroll
    for (int o = 1; o < 32; o <<= 1) {
        int u = __shfl_up_sync(0xFFFFFFFFu, inc, o);
        if (lane >= o) inc += u;
    }
    if (lane == 31) wsum[wid] = inc;
    __syncthreads();
    if (t < 8) {
        int val = wsum[t];
        int ic = val;
        #pragma unroll
        for (int o = 1; o < 8; o <<= 1) {
            int u = __shfl_up_sync(0xFFu, ic, o);
            if (t >= o) ic += u;
        }
        wexc[t] = ic - val;
    }
    __syncthreads();
    int thOff = d_boff[blockIdx.x] + wexc[wid] + (inc - c);
    int U = pb[BATCH];

    unsigned* hw = (unsigned*)d_h;  // low words: rank storage

    #pragma unroll
    for (int e = 0; e < ITEMS; e++) {
        int i   = i0 + e;
        int isf = (int)((w[e >> 2] >> ((e & 3) * 8)) & 1);
        int p   = thOff + pre[e];
        int b   = i >> 17;
        int il  = i & (NPTS - 1);
        int r   = p - pb[b];
        int Kb  = pb[b + 1] - pb[b];
        int sel;
        if (isf) {
            hw[2 * ss[e]] = (unsigned)p;        // appearance rank into hash low word
            out[OFF_ULI + p] = (float)i;        // ul_idx_inv (p monotone in i)
            sel = (r < TSEL) ? r : -1;
        } else {
            int tt = Kb + (il - r);
            sel = (tt < TSEL) ? tt : -1;
        }
        if (i >= U) out[OFF_ULI + i] = (float)BN;   // SENT tail
        if (sel >= 0) {
            float y0 = CELL * rintf(__fdiv_rn(__ldg(&x[3*i+0]), CELL));
            float y1 = CELL * rintf(__fdiv_rn(__ldg(&x[3*i+1]), CELL));
            float y2 = CELL * rintf(__fdiv_rn(__ldg(&x[3*i+2]), CELL));
            int o = b * TSEL + sel;
            out[OFF_Y + 3*o + 0] = y0;
            out[OFF_Y + 3*o + 1] = y1;
            out[OFF_Y + 3*o + 2] = y2;
            out[OFF_IDX + 2*o + 0] = (float)b;
            out[OFF_IDX + 2*o + 1] = (float)il;
            out[OFF_MASK + o] = isf ? 1.0f : 0.0f;
        }
    }
}

// ---------------------------------------------------------------------------
// K6: ul_idx gather, 4 points per thread (independent gathers, good MLP)
__global__ void k_ulidx(float* __restrict__ out) {
    int j = blockIdx.x * blockDim.x + threadIdx.x;   // [0, BN/4)
    int base = 4 * j;
    const unsigned* hw = (const unsigned*)d_h;
    int4 sl = *(const int4*)(d_slot + base);
    float r0 = (float)__ldcg(hw + 2*sl.x);
    float r1 = (float)__ldcg(hw + 2*sl.y);
    float r2 = (float)__ldcg(hw + 2*sl.z);
    float r3 = (float)__ldcg(hw + 2*sl.w);
    *(float4*)(out + OFF_UL + base) = make_float4(r0, r1, r2, r3);
}

// ---------------------------------------------------------------------------
extern "C" void kernel_launch(void* const* d_in, const int* in_sizes, int n_in,
                              void* d_out, int out_size) {
    const float* x = (const float*)d_in[0];
    float* out = (float*)d_out;
    (void)in_sizes; (void)n_in; (void)out_size;

    k_init  <<<2048, 512>>>();
    k_insert<<<BN / 256, 256>>>(x);
    k_flags <<<NBLK, SCANT>>>();
    k_scan2 <<<1, NBLK>>>();
    k_final <<<NBLK, SCANT>>>(x, out);
    k_ulidx <<<BN / 4 / 256, 256>>>(out);
}

// round 4
// speedup vs baseline: 1.3386x; 1.0104x over previous
#include <cuda_runtime.h>
#include <limits.h>
#include <stdint.h>

typedef unsigned long long u64;

// Problem constants
#define BATCH 32
#define NPTS  131072            // 2^17
#define BN    (BATCH*NPTS)      // 4194304
#define TSEL  32768
#define CELL  0.05f

// Hash: 2^23 slots of one u64 (key<<32 | minIndex), load factor <= 0.5
#define HBITS 23
#define HSIZE (1<<HBITS)
#define HMASK (HSIZE-1)
#define EMPTY64 0xFFFFFFFFFFFFFFFFull

// Scan config: 1024 blocks x 4096 elements (256 thr x 16)
#define NBLK  1024
#define CHUNK 4096
#define SCANT 256
#define ITEMS 16

// Output layout (flattened, concatenated, all f32)
#define OFF_Y    0
#define OFF_IDX  (BATCH*TSEL*3)
#define OFF_MASK (OFF_IDX + BATCH*TSEL*2)
#define OFF_UL   (OFF_MASK + BATCH*TSEL)
#define OFF_ULI  (OFF_UL + BN)

// Scratch
__device__ u64 d_h[HSIZE];             // (key<<32)|minIdx ; low word later = rank
__device__ int d_slot[BN];
__device__ unsigned char d_flag[BN];
__device__ int d_bsum[NBLK];
__device__ int d_boff[NBLK];
__device__ int d_pbatch[BATCH+1];

__device__ __forceinline__ int quant(float v) {
    return (int)rintf(__fdiv_rn(v, CELL));
}
__device__ __forceinline__ unsigned mkkey(int b, int q0, int q1, int q2) {
    return ((unsigned)b << 27) | ((unsigned)(q0 + 256) << 18)
         | ((unsigned)(q1 + 256) << 9) | (unsigned)(q2 + 256);
}
__device__ __forceinline__ unsigned khash(unsigned k) {
    return (k * 2654435761u) >> (32 - HBITS);
}

// ---------------------------------------------------------------------------
// K1: init hash table to EMPTY
__global__ void k_init() {
    unsigned i = blockIdx.x * blockDim.x + threadIdx.x;
    unsigned stride = gridDim.x * blockDim.x;
    ulonglong2* p = (ulonglong2*)d_h;
    const unsigned n = HSIZE / 2;
    for (unsigned j = i; j < n; j += stride)
        p[j] = make_ulonglong2(EMPTY64, EMPTY64);
}

// ---------------------------------------------------------------------------
// K2: insert, CAS-first probing (CAS's return value doubles as the read)
__global__ void k_insert(const float* __restrict__ x) {
    int i = blockIdx.x * blockDim.x + threadIdx.x;   // [0, BN)
    float x0 = __ldg(&x[3*i+0]);
    float x1 = __ldg(&x[3*i+1]);
    float x2 = __ldg(&x[3*i+2]);
    int q0 = quant(x0), q1 = quant(x1), q2 = quant(x2);
    int b = i >> 17;
    unsigned key = mkkey(b, q0, q1, q2);
    u64 val = ((u64)key << 32) | (unsigned)i;
    unsigned h = khash(key);
    while (true) {
        u64 old = atomicCAS(&d_h[h], EMPTY64, val);
        if (old == EMPTY64) break;                        // claimed
        if ((unsigned)(old >> 32) == key) {
            if ((unsigned)old > (unsigned)i)              // only if we could lower it
                atomicMin(&d_h[h], val);
            break;
        }
        h = (h + 1) & HMASK;
    }
    d_slot[i] = (int)h;
}

// ---------------------------------------------------------------------------
// K3: first-occurrence flags (packed 16B store) + per-block sums
__global__ void k_flags() {
    int t = threadIdx.x;
    int i0 = blockIdx.x * CHUNK + t * ITEMS;
    int s = 0;
    unsigned fw[4];
    #pragma unroll
    for (int v = 0; v < 4; v++) {
        int4 sl = *(const int4*)(d_slot + i0 + 4*v);
        u64 c0 = __ldcg(&d_h[sl.x]);
        u64 c1 = __ldcg(&d_h[sl.y]);
        u64 c2 = __ldcg(&d_h[sl.z]);
        u64 c3 = __ldcg(&d_h[sl.w]);
        unsigned f0 = ((unsigned)c0 == (unsigned)(i0 + 4*v + 0));
        unsigned f1 = ((unsigned)c1 == (unsigned)(i0 + 4*v + 1));
        unsigned f2 = ((unsigned)c2 == (unsigned)(i0 + 4*v + 2));
        unsigned f3 = ((unsigned)c3 == (unsigned)(i0 + 4*v + 3));
        fw[v] = f0 | (f1 << 8) | (f2 << 16) | (f3 << 24);
        s += (int)(f0 + f1 + f2 + f3);
    }
    *(uint4*)(d_flag + i0) = make_uint4(fw[0], fw[1], fw[2], fw[3]);

    #pragma unroll
    for (int o = 16; o; o >>= 1) s += __shfl_xor_sync(0xFFFFFFFFu, s, o);
    __shared__ int ws[8];
    int lane = t & 31, wid = t >> 5;
    if (lane == 0) ws[wid] = s;
    __syncthreads();
    if (t == 0) {
        int tot = 0;
        #pragma unroll
        for (int k = 0; k < 8; k++) tot += ws[k];
        d_bsum[blockIdx.x] = tot;
    }
}

// ---------------------------------------------------------------------------
// K4: warp-shuffle scan of the 1024 block sums
__global__ void k_scan2() {
    __shared__ int wsum[32];
    int t = threadIdx.x;
    int lane = t & 31, wid = t >> 5;
    int v = d_bsum[t];
    int inc = v;
    #pragma unroll
    for (int o = 1; o < 32; o <<= 1) {
        int u = __shfl_up_sync(0xFFFFFFFFu, inc, o);
        if (lane >= o) inc += u;
    }
    if (lane == 31) wsum[wid] = inc;
    __syncthreads();
    if (t < 32) {
        int wv = wsum[t];
        int wi = wv;
        #pragma unroll
        for (int o = 1; o < 32; o <<= 1) {
            int u = __shfl_up_sync(0xFFFFFFFFu, wi, o);
            if (t >= o) wi += u;
        }
        wsum[t] = wi - wv;   // exclusive warp offset
    }
    __syncthreads();
    int incl = inc + wsum[wid];
    int excl = incl - v;
    d_boff[t] = excl;
    if ((t & 31) == 0) d_pbatch[t >> 5] = excl;   // 32 blocks per batch
    if (t == NBLK - 1) d_pbatch[BATCH] = incl;
}

// ---------------------------------------------------------------------------
// K5: final — prefix per point, rank scatter (hash low word), ul_idx_inv +
//     SENT tail, ul_idx for FIRSTS (rank known locally), top-T select
__global__ void k_final(const float* __restrict__ x, float* __restrict__ out) {
    __shared__ int pb[BATCH + 1];
    __shared__ int wsum[8];
    __shared__ int wexc[8];
    int t = threadIdx.x;
    if (t <= BATCH) pb[t] = d_pbatch[t];

    int i0 = blockIdx.x * CHUNK + t * ITEMS;
    uint4 v4 = *(const uint4*)(d_flag + i0);
    unsigned w[4] = {v4.x, v4.y, v4.z, v4.w};

    int ss[ITEMS];
    #pragma unroll
    for (int v = 0; v < 4; v++) {
        int4 sv = *(const int4*)(d_slot + i0 + 4*v);
        ss[4*v+0] = sv.x; ss[4*v+1] = sv.y; ss[4*v+2] = sv.z; ss[4*v+3] = sv.w;
    }

    int pre[ITEMS];
    int c = 0;
    #pragma unroll
    for (int e = 0; e < ITEMS; e++) {
        pre[e] = c;
        c += (int)((w[e >> 2] >> ((e & 3) * 8)) & 1);
    }
    int lane = t & 31, wid = t >> 5;
    int inc = c;
    #pragma unroll
    for (int o = 1; o < 32; o <<= 1) {
        int u = __shfl_up_sync(0xFFFFFFFFu, inc, o);
        if (lane >= o) inc += u;
    }
    if (lane == 31) wsum[wid] = inc;
    __syncthreads();
    if (t < 8) {
        int val = wsum[t];
        int ic = val;
        #pragma unroll
        for (int o = 1; o < 8; o <<= 1) {
            int u = __shfl_up_sync(0xFFu, ic, o);
            if (t >= o) ic += u;
        }
        wexc[t] = ic - val;
    }
    __syncthreads();
    int thOff = d_boff[blockIdx.x] + wexc[wid] + (inc - c);
    int U = pb[BATCH];

    unsigned* hw = (unsigned*)d_h;  // low words: rank storage

    #pragma unroll
    for (int e = 0; e < ITEMS; e++) {
        int i   = i0 + e;
        int isf = (int)((w[e >> 2] >> ((e & 3) * 8)) & 1);
        int p   = thOff + pre[e];
        int b   = i >> 17;
        int il  = i & (NPTS - 1);
        int r   = p - pb[b];
        int Kb  = pb[b + 1] - pb[b];
        int sel;
        if (isf) {
            hw[2 * ss[e]] = (unsigned)p;        // appearance rank into hash low word
            out[OFF_ULI + p] = (float)i;        // ul_idx_inv (p monotone in i)
            out[OFF_UL + i]  = (float)p;        // ul_idx for firsts: own rank
            sel = (r < TSEL) ? r : -1;
        } else {
            int tt = Kb + (il - r);
            sel = (tt < TSEL) ? tt : -1;
        }
        if (i >= U) out[OFF_ULI + i] = (float)BN;   // SENT tail
        if (sel >= 0) {
            float y0 = CELL * rintf(__fdiv_rn(__ldg(&x[3*i+0]), CELL));
            float y1 = CELL * rintf(__fdiv_rn(__ldg(&x[3*i+1]), CELL));
            float y2 = CELL * rintf(__fdiv_rn(__ldg(&x[3*i+2]), CELL));
            int o = b * TSEL + sel;
            out[OFF_Y + 3*o + 0] = y0;
            out[OFF_Y + 3*o + 1] = y1;
            out[OFF_Y + 3*o + 2] = y2;
            out[OFF_IDX + 2*o + 0] = (float)b;
            out[OFF_IDX + 2*o + 1] = (float)il;
            out[OFF_MASK + o] = isf ? 1.0f : 0.0f;
        }
    }
}

// ---------------------------------------------------------------------------
// K6: ul_idx gather for NON-FIRSTS only (~10% of points)
__global__ void k_ulidx(float* __restrict__ out) {
    int t = threadIdx.x;
    int i0 = blockIdx.x * CHUNK + t * ITEMS;
    const unsigned* hw = (const unsigned*)d_h;
    uint4 v4 = *(const uint4*)(d_flag + i0);
    unsigned w[4] = {v4.x, v4.y, v4.z, v4.w};
    #pragma unroll
    for (int v = 0; v < 4; v++) {
        unsigned fw = w[v];
        if (fw == 0x01010101u) continue;         // all firsts: already written
        int4 sl = *(const int4*)(d_slot + i0 + 4*v);
        int slots[4] = {sl.x, sl.y, sl.z, sl.w};
        #pragma unroll
        for (int e = 0; e < 4; e++) {
            if (((fw >> (e * 8)) & 1) == 0) {
                unsigned rank = __ldcg(hw + 2 * slots[e]);
                out[OFF_UL + i0 + 4*v + e] = (float)rank;
            }
        }
    }
}

// ---------------------------------------------------------------------------
extern "C" void kernel_launch(void* const* d_in, const int* in_sizes, int n_in,
                              void* d_out, int out_size) {
    const float* x = (const float*)d_in[0];
    float* out = (float*)d_out;
    (void)in_sizes; (void)n_in; (void)out_size;

    k_init  <<<2048, 512>>>();
    k_insert<<<BN / 256, 256>>>(x);
    k_flags <<<NBLK, SCANT>>>();
    k_scan2 <<<1, NBLK>>>();
    k_final <<<NBLK, SCANT>>>(x, out);
    k_ulidx <<<NBLK, SCANT>>>(out);
}

// round 5
// speedup vs baseline: 1.4551x; 1.0871x over previous
#include <cuda_runtime.h>
#include <limits.h>
#include <stdint.h>

typedef unsigned long long u64;

// Problem constants
#define BATCH 32
#define NPTS  131072            // 2^17
#define BN    (BATCH*NPTS)      // 4194304
#define TSEL  32768
#define CELL  0.05f

// Hash: 2^23 slots of one u64 (key<<32 | minIdx); high word later = rank
#define HBITS 23
#define HSIZE (1<<HBITS)
#define HMASK (HSIZE-1)
#define EMPTY64 0xFFFFFFFFFFFFFFFFull

// Scan config: 1024 blocks x 4096 elements (256 thr x 16)
#define NBLK  1024
#define CHUNK 4096
#define SCANT 256
#define ITEMS 16

// Lookback state flags
#define FLAG1 (1ull << 62)       // aggregate available
#define FLAG2 (2ull << 62)       // inclusive available
#define SFMASK (3ull << 62)
#define PUBBIT (1ull << 63)      // bbase published
#define VALMASK 0x3FFFFFFFull

// Output layout (flattened, concatenated, all f32)
#define OFF_Y    0
#define OFF_IDX  (BATCH*TSEL*3)
#define OFF_MASK (OFF_IDX + BATCH*TSEL*2)
#define OFF_UL   (OFF_MASK + BATCH*TSEL)
#define OFF_ULI  (OFF_UL + BN)

// Scratch
__device__ u64 d_h[HSIZE];             // low: (key->) stays minIdx ; HIGH word becomes rank
__device__ int d_slot[BN];
__device__ unsigned char d_flag[BN];
__device__ u64 d_state[NBLK];
__device__ u64 d_bbase[BATCH+1];
__device__ unsigned d_ticket;

__device__ __forceinline__ int quant(float v) {
    return (int)rintf(__fdiv_rn(v, CELL));
}
__device__ __forceinline__ unsigned mkkey(int b, int q0, int q1, int q2) {
    return ((unsigned)b << 27) | ((unsigned)(q0 + 256) << 18)
         | ((unsigned)(q1 + 256) << 9) | (unsigned)(q2 + 256);
}
__device__ __forceinline__ unsigned khash(unsigned k) {
    return (k * 2654435761u) >> (32 - HBITS);
}

// ---------------------------------------------------------------------------
// K1: init hash table + lookback state
__global__ void k_init() {
    unsigned i = blockIdx.x * blockDim.x + threadIdx.x;
    unsigned stride = gridDim.x * blockDim.x;
    ulonglong2* p = (ulonglong2*)d_h;
    const unsigned n = HSIZE / 2;
    for (unsigned j = i; j < n; j += stride)
        p[j] = make_ulonglong2(EMPTY64, EMPTY64);
    if (i < NBLK) d_state[i] = 0;
    if (i <= BATCH) d_bbase[i] = 0;
    if (i == 0) d_ticket = 0;
}

// ---------------------------------------------------------------------------
// K2: insert, CAS-first probing
__global__ void k_insert(const float* __restrict__ x) {
    int i = blockIdx.x * blockDim.x + threadIdx.x;   // [0, BN)
    float x0 = __ldg(&x[3*i+0]);
    float x1 = __ldg(&x[3*i+1]);
    float x2 = __ldg(&x[3*i+2]);
    int q0 = quant(x0), q1 = quant(x1), q2 = quant(x2);
    int b = i >> 17;
    unsigned key = mkkey(b, q0, q1, q2);
    u64 val = ((u64)key << 32) | (unsigned)i;
    unsigned h = khash(key);
    while (true) {
        u64 old = atomicCAS(&d_h[h], EMPTY64, val);
        if (old == EMPTY64) break;
        if ((unsigned)(old >> 32) == key) {
            if ((unsigned)old > (unsigned)i)
                atomicMin(&d_h[h], val);
            break;
        }
        h = (h + 1) & HMASK;
    }
    d_slot[i] = (int)h;
}

// ---------------------------------------------------------------------------
// K3: fused flags + decoupled-lookback scan + all main scatters
__global__ void __launch_bounds__(SCANT) k_fused(const float* __restrict__ x,
                                                 float* __restrict__ out) {
    __shared__ int s_tb;
    __shared__ int wsum[8];
    __shared__ int wexc[8];
    __shared__ int s_total;
    __shared__ unsigned s_excl, s_pb;

    int t = threadIdx.x;
    if (t == 0) s_tb = (int)atomicAdd(&d_ticket, 1u);
    __syncthreads();
    int tb = s_tb;
    int i0 = tb * CHUNK + t * ITEMS;

    const unsigned* hlow = (const unsigned*)d_h;   // low words (even indices)

    int ss[ITEMS];
    #pragma unroll
    for (int v = 0; v < 4; v++) {
        int4 sv = *(const int4*)(d_slot + i0 + 4*v);
        ss[4*v+0] = sv.x; ss[4*v+1] = sv.y; ss[4*v+2] = sv.z; ss[4*v+3] = sv.w;
    }
    unsigned fw[4];
    int c = 0;
    int pre[ITEMS];
    #pragma unroll
    for (int v = 0; v < 4; v++) {
        unsigned f0 = (__ldcg(hlow + 2*ss[4*v+0]) == (unsigned)(i0 + 4*v + 0));
        unsigned f1 = (__ldcg(hlow + 2*ss[4*v+1]) == (unsigned)(i0 + 4*v + 1));
        unsigned f2 = (__ldcg(hlow + 2*ss[4*v+2]) == (unsigned)(i0 + 4*v + 2));
        unsigned f3 = (__ldcg(hlow + 2*ss[4*v+3]) == (unsigned)(i0 + 4*v + 3));
        fw[v] = f0 | (f1 << 8) | (f2 << 16) | (f3 << 24);
        pre[4*v+0] = c; c += (int)f0;
        pre[4*v+1] = c; c += (int)f1;
        pre[4*v+2] = c; c += (int)f2;
        pre[4*v+3] = c; c += (int)f3;
    }
    *(uint4*)(d_flag + i0) = make_uint4(fw[0], fw[1], fw[2], fw[3]);

    // block scan of per-thread counts
    int lane = t & 31, wid = t >> 5;
    int inc = c;
    #pragma unroll
    for (int o = 1; o < 32; o <<= 1) {
        int u = __shfl_up_sync(0xFFFFFFFFu, inc, o);
        if (lane >= o) inc += u;
    }
    if (lane == 31) wsum[wid] = inc;
    __syncthreads();
    if (t < 8) {
        int val = wsum[t];
        int ic = val;
        #pragma unroll
        for (int o = 1; o < 8; o <<= 1) {
            int u = __shfl_up_sync(0xFFu, ic, o);
            if (t >= o) ic += u;
        }
        wexc[t] = ic - val;
        if (t == 7) s_total = ic;
    }
    __syncthreads();
    int agg = s_total;

    // decoupled lookback (thread 0)
    if (t == 0) {
        unsigned excl = 0;
        if (tb == 0) {
            __threadfence();
            atomicExch(&d_state[0], FLAG2 | (u64)agg);
        } else {
            atomicExch(&d_state[tb], FLAG1 | (u64)agg);
            int j = tb - 1;
            while (true) {
                u64 s = *(volatile u64*)&d_state[j];
                u64 f = s & SFMASK;
                if (f == 0) continue;
                excl += (unsigned)(s & VALMASK);
                if (f == FLAG2) break;
                j--;
            }
            __threadfence();
            atomicExch(&d_state[tb], FLAG2 | (u64)(excl + (unsigned)agg));
        }
        int m = tb >> 5;
        unsigned pb;
        if ((tb & 31) == 0) {
            __threadfence();
            atomicExch(&d_bbase[m], PUBBIT | (u64)excl);
            pb = excl;
        } else {
            while (true) {
                u64 s = *(volatile u64*)&d_bbase[m];
                if (s & PUBBIT) { pb = (unsigned)(s & VALMASK); break; }
            }
        }
        if (tb == NBLK - 1) {
            __threadfence();
            atomicExch(&d_bbase[BATCH], PUBBIT | (u64)(excl + (unsigned)agg));
        }
        s_excl = excl;
        s_pb = pb;
    }
    __syncthreads();

    int thOff = (int)s_excl + wexc[wid] + (inc - c);
    int pb = (int)s_pb;
    int b = tb >> 5;
    unsigned* hw = (unsigned*)d_h;   // high words at odd indices: rank storage

    #pragma unroll
    for (int e = 0; e < ITEMS; e++) {
        int isf = (int)((fw[e >> 2] >> ((e & 3) * 8)) & 1);
        if (isf) {
            int i  = i0 + e;
            int p  = thOff + pre[e];
            hw[2 * ss[e] + 1] = (unsigned)p;     // rank -> HIGH word (low stays minIdx)
            out[OFF_ULI + p]  = (float)i;
            out[OFF_UL + i]   = (float)p;
            int r = p - pb;
            if (r < TSEL) {
                int il = i & (NPTS - 1);
                float y0 = CELL * rintf(__fdiv_rn(__ldg(&x[3*i+0]), CELL));
                float y1 = CELL * rintf(__fdiv_rn(__ldg(&x[3*i+1]), CELL));
                float y2 = CELL * rintf(__fdiv_rn(__ldg(&x[3*i+2]), CELL));
                int o = b * TSEL + r;
                out[OFF_Y + 3*o + 0] = y0;
                out[OFF_Y + 3*o + 1] = y1;
                out[OFF_Y + 3*o + 2] = y2;
                out[OFF_IDX + 2*o + 0] = (float)b;
                out[OFF_IDX + 2*o + 1] = (float)il;
                out[OFF_MASK + o] = 1.0f;
            }
        }
    }
}

// ---------------------------------------------------------------------------
// K4: ul_idx gather for non-firsts (rank = hash HIGH word)
__global__ void k_ulidx(float* __restrict__ out) {
    int t = threadIdx.x;
    int i0 = blockIdx.x * CHUNK + t * ITEMS;
    const unsigned* hw = (const unsigned*)d_h;
    uint4 v4 = *(const uint4*)(d_flag + i0);
    unsigned w[4] = {v4.x, v4.y, v4.z, v4.w};
    #pragma unroll
    for (int v = 0; v < 4; v++) {
        unsigned fwv = w[v];
        if (fwv == 0x01010101u) continue;
        int4 sl = *(const int4*)(d_slot + i0 + 4*v);
        int slots[4] = {sl.x, sl.y, sl.z, sl.w};
        #pragma unroll
        for (int e = 0; e < 4; e++) {
            if (((fwv >> (e * 8)) & 1) == 0) {
                unsigned rank = __ldcg(hw + 2 * slots[e] + 1);
                out[OFF_UL + i0 + 4*v + e] = (float)rank;
            }
        }
    }
}

// ---------------------------------------------------------------------------
// K5: fixup — ULI SENT tail + (dormant) deficient-batch non-first fill
__global__ void k_fixup(const float* __restrict__ x, float* __restrict__ out) {
    int blk = blockIdx.x;
    int t = threadIdx.x;
    if (blk >= BATCH) {
        // SENT tail: i in [U, BN)
        int U = (int)(d_bbase[BATCH] & VALMASK);
        int nb = gridDim.x - BATCH;
        for (int i = U + (blk - BATCH) * blockDim.x + t; i < BN; i += nb * blockDim.x)
            out[OFF_ULI + i] = (float)BN;
        return;
    }
    int pb0 = (int)(d_bbase[blk] & VALMASK);
    int pb1 = (int)(d_bbase[blk + 1] & VALMASK);
    int Kb = pb1 - pb0;
    if (Kb >= TSEL) return;   // normal case: all TSEL slots already filled by firsts

    // Dormant slow path: sequential chunked scan over this batch's points
    __shared__ int s_run;
    __shared__ int cw[8];
    if (t == 0) s_run = 0;
    __syncthreads();
    for (int base = 0; base < NPTS; base += SCANT) {
        int il = base + t;
        int i = blk * NPTS + il;
        int isf = (int)d_flag[i];
        int lane = t & 31, wid = t >> 5;
        int incv = isf;
        #pragma unroll
        for (int o = 1; o < 32; o <<= 1) {
            int u = __shfl_up_sync(0xFFFFFFFFu, incv, o);
            if (lane >= o) incv += u;
        }
        if (lane == 31) cw[wid] = incv;
        __syncthreads();
        int woff = 0;
        for (int k = 0; k < wid; k++) woff += cw[k];
        int r = s_run + woff + incv - isf;   // firsts strictly before il
        if (!isf) {
            int tt = Kb + (il - r);
            if (tt < TSEL) {
                float y0 = CELL * rintf(__fdiv_rn(__ldg(&x[3*i+0]), CELL));
                float y1 = CELL * rintf(__fdiv_rn(__ldg(&x[3*i+1]), CELL));
                float y2 = CELL * rintf(__fdiv_rn(__ldg(&x[3*i+2]), CELL));
                int o = blk * TSEL + tt;
                out[OFF_Y + 3*o + 0] = y0;
                out[OFF_Y + 3*o + 1] = y1;
                out[OFF_Y + 3*o + 2] = y2;
                out[OFF_IDX + 2*o + 0] = (float)blk;
                out[OFF_IDX + 2*o + 1] = (float)il;
                out[OFF_MASK + o] = 0.0f;
            }
        }
        __syncthreads();
        if (t == 0) {
            int tot = 0;
            #pragma unroll
            for (int k = 0; k < 8; k++) tot += cw[k];
            s_run += tot;
        }
        __syncthreads();
    }
}

// ---------------------------------------------------------------------------
extern "C" void kernel_launch(void* const* d_in, const int* in_sizes, int n_in,
                              void* d_out, int out_size) {
    const float* x = (const float*)d_in[0];
    float* out = (float*)d_out;
    (void)in_sizes; (void)n_in; (void)out_size;

    k_init  <<<2048, 512>>>();
    k_insert<<<BN / 256, 256>>>(x);
    k_fused <<<NBLK, SCANT>>>(x, out);
    k_ulidx <<<NBLK, SCANT>>>(out);
    k_fixup <<<BATCH + 64, SCANT>>>(x, out);
}